// round 12
// baseline (speedup 1.0000x reference)
#include <cuda_runtime.h>
#include <cstddef>
#include <cstdint>

// Problem constants: B=256, L=20, V=9488, S=18
#define BB 256
#define LL 20
#define VV 9488
#define SS 18
#define TLEN (LL - 1)        // 19
#define NBLK 128
#define WARPS_PER_BLK 2      // 128 blocks * 2 warps = 256 warps = 256 rows
#define NWARPS (NBLK * WARPS_PER_BLK)

// Fixed point: per-lane scale 2^20, per-lane bias 2^25 (u32 warp sums),
// per-warp bias 2^33 in the 42-bit global sum field.
#define FP_SCALE   1048576.0f            // 2^20
#define FP_INVSCAL (1.0f / 1048576.0f)
#define LANE_BIAS  (1 << 25)
#define WARP_LBIAS (1ll << 30)           // 32 * 2^25
#define WARP_GBIAS (1ll << 33)
#define TOTAL_BIAS (1ll << 41)           // 256 * 2^33
#define SUM_MASK   ((1ull << 42) - 1ull)
#define CNT_SHIFT  42
#define ARR_SHIFT  55

__device__ unsigned long long g_acc = 0ull;   // zero-init; self-reset per launch

__device__ __forceinline__ unsigned redux_add_u32(unsigned v) {
    unsigned r;
    asm volatile("redux.sync.add.u32 %0, %1, 0xffffffff;" : "=r"(r) : "r"(v));
    return r;
}

__global__ __launch_bounds__(64, 1)
void scst_onepass_kernel(const float* __restrict__ inp,
                         const int*   __restrict__ tgt,
                         const float* __restrict__ reward,
                         const float* __restrict__ reward1,
                         float* __restrict__ out) {
    const int tid  = threadIdx.x;
    const int w    = tid >> 5;
    const int lane = tid & 31;
    const int b    = blockIdx.x * WARPS_PER_BLK + w;    // batch row

    // 1) Critical load FIRST: padded target at position lane
    //    (target[b][lane] for lane<18, else 0 — lane 18 is the zero pad)
    int tv = 0;
    if (lane < SS) tv = tgt[b * SS + lane];

    // 2) Independent reward prefetch AFTER the tgt LDG has dispatched
    //    (any warp can be the 256th arriver, so every lane 0 loads them)
    float rw = 0.0f, rw1 = 0.0f;
    if (lane == 0) { rw = reward[0]; rw1 = reward1[0]; }

    // 3) SPECULATIVE gather: issue as soon as tv arrives — always in-bounds
    //    for lane<19 (tv=0 for the pad lane). Mask applied after the fact.
    const bool active = (lane < TLEN);
    float val = 0.0f;
    if (active) {
        val = inp[(size_t)b * (size_t)(LL * VV)
                + (size_t)(lane + 1) * (size_t)VV
                + (size_t)tv];
    }

    // 4) Ballot/keep-count computed WHILE the gather is in flight.
    //    kept set is the prefix {0..cnt-1}: cnt = index of 2nd zero, else 19
    const unsigned zball = __ballot_sync(0xFFFFFFFFu, active && (tv == 0));
    const unsigned z2    = zball & (zball - 1u);
    const unsigned cnt   = z2 ? (unsigned)(__ffs((int)z2) - 1) : (unsigned)TLEN;

    // 5) Post-hoc mask, then fixed-point warp reduce (one HW redux)
    val = ((unsigned)lane < cnt) ? val : 0.0f;
    const int      fx  = __float2int_rn(val * FP_SCALE);   // |val|<32 -> |fx|<2^25
    const unsigned fxb = (unsigned)(fx + LANE_BIAS);       // in [0, 2^26)
    const unsigned s   = redux_add_u32(fxb);               // < 2^31, uniform

    if (lane == 0) {
        const long long warp_fx = (long long)s - WARP_LBIAS;   // scale 2^20
        const unsigned long long addend =
              (1ull << ARR_SHIFT)
            | ((unsigned long long)cnt << CNT_SHIFT)
            | (unsigned long long)(warp_fx + WARP_GBIAS);

        // single-level packed arrival; full result rides the atomic return
        const unsigned long long prev = atomicAdd(&g_acc, addend);
        if ((prev >> ARR_SHIFT) == (unsigned long long)(NWARPS - 1)) {
            const unsigned long long tot = prev + addend;
            const long long sumfx = (long long)(tot & SUM_MASK) - TOTAL_BIAS;
            const float    v = (float)sumfx * FP_INVSCAL;
            const unsigned c = (unsigned)((tot >> CNT_SHIFT) & 0x1FFFu);

            float rd = rw - rw1;
            if (rd < 1.0f) rd = 1.0f;
            out[0] = -(v / (float)c) * rd;

            atomicExch(&g_acc, 0ull);   // reset for next graph replay (off-path)
        }
    }
}

extern "C" void kernel_launch(void* const* d_in, const int* in_sizes, int n_in,
                              void* d_out, int out_size) {
    const float* inp     = (const float*)d_in[0];   // [B, L, V] f32
    const int*   tgt     = (const int*)  d_in[1];   // [B, S]    i32
    const float* reward  = (const float*)d_in[2];   // [1]       f32
    const float* reward1 = (const float*)d_in[3];   // [1]       f32
    float*       out     = (float*)d_out;           // [1]       f32

    scst_onepass_kernel<<<NBLK, 64>>>(inp, tgt, reward, reward1, out);
}

// round 13
// speedup vs baseline: 1.0386x; 1.0386x over previous
#include <cuda_runtime.h>
#include <cstddef>
#include <cstdint>

// Problem constants: B=256, L=20, V=9488, S=18
#define BB 256
#define LL 20
#define VV 9488
#define SS 18
#define TLEN (LL - 1)        // 19
#define NBLK 32
#define WARPS_PER_BLK 8      // 256 warps = 256 rows
#define NWARPS (NBLK * WARPS_PER_BLK)

// Fixed point: per-lane scale 2^20, per-lane bias 2^25 (u32 warp sums),
// per-warp bias 2^33 in the 42-bit global sum field.
#define FP_SCALE   1048576.0f            // 2^20
#define FP_INVSCAL (1.0f / 1048576.0f)
#define LANE_BIAS  (1 << 25)
#define WARP_LBIAS (1ll << 30)           // 32 * 2^25
#define WARP_GBIAS (1ll << 33)
#define TOTAL_BIAS (1ll << 41)           // 256 * 2^33
#define SUM_MASK   ((1ull << 42) - 1ull)
#define CNT_SHIFT  42
#define ARR_SHIFT  55

__device__ unsigned long long g_acc = 0ull;   // zero-init; self-reset per launch

__device__ __forceinline__ unsigned redux_add_u32(unsigned v) {
    unsigned r;
    asm volatile("redux.sync.add.u32 %0, %1, 0xffffffff;" : "=r"(r) : "r"(v));
    return r;
}

__global__ __launch_bounds__(256, 1)
void scst_onepass_kernel(const float* __restrict__ inp,
                         const int*   __restrict__ tgt,
                         const float* __restrict__ reward,
                         const float* __restrict__ reward1,
                         float* __restrict__ out) {
    const int tid  = threadIdx.x;
    const int w    = tid >> 5;
    const int lane = tid & 31;
    const int b    = blockIdx.x * WARPS_PER_BLK + w;    // batch row

    // 1) Critical load FIRST: minimal address math, then the tgt LDG.
    //    padded target at position lane: target[b][lane] for lane<18, else 0.
    const int* tgt_row = tgt + b * SS;
    int tv = 0;
    if (lane < SS) tv = tgt_row[lane];

    // 2) Gather base for this (row, timestep) — independent of tv, computed
    //    while the tgt load is in flight: &inp[b*L*V + (lane+1)*V]
    const float* gbase = inp + (size_t)b * (size_t)(LL * VV)
                             + (size_t)(lane + 1) * (size_t)VV;

    // 3) Independent reward prefetch (any warp can be the 256th arriver)
    float rw = 0.0f, rw1 = 0.0f;
    if (lane == 0) { rw = reward[0]; rw1 = reward1[0]; }

    // 4) SPECULATIVE gather: issues the cycle tv lands (addr = gbase + tv).
    //    Always in-bounds for lane<19 (pad lane has tv=0). Masked post-hoc.
    const bool active = (lane < TLEN);
    float val = 0.0f;
    if (active) val = gbase[tv];

    // 5) Ballot/keep-count computed WHILE the gather is in flight.
    //    kept set is the prefix {0..cnt-1}: cnt = index of 2nd zero, else 19
    const unsigned zball = __ballot_sync(0xFFFFFFFFu, active && (tv == 0));
    const unsigned z2    = zball & (zball - 1u);
    const unsigned cnt   = z2 ? (unsigned)(__ffs((int)z2) - 1) : (unsigned)TLEN;

    // 6) Post-hoc mask, then fixed-point warp reduce (one HW redux)
    val = ((unsigned)lane < cnt) ? val : 0.0f;
    const int      fx  = __float2int_rn(val * FP_SCALE);   // |val|<32 -> |fx|<2^25
    const unsigned fxb = (unsigned)(fx + LANE_BIAS);       // in [0, 2^26)
    const unsigned s   = redux_add_u32(fxb);               // < 2^31, uniform

    if (lane == 0) {
        const long long warp_fx = (long long)s - WARP_LBIAS;   // scale 2^20
        const unsigned long long addend =
              (1ull << ARR_SHIFT)
            | ((unsigned long long)cnt << CNT_SHIFT)
            | (unsigned long long)(warp_fx + WARP_GBIAS);

        // single-level packed arrival; full result rides the atomic return
        const unsigned long long prev = atomicAdd(&g_acc, addend);
        if ((prev >> ARR_SHIFT) == (unsigned long long)(NWARPS - 1)) {
            const unsigned long long tot = prev + addend;
            const long long sumfx = (long long)(tot & SUM_MASK) - TOTAL_BIAS;
            const float    v = (float)sumfx * FP_INVSCAL;
            const unsigned c = (unsigned)((tot >> CNT_SHIFT) & 0x1FFFu);

            float rd = rw - rw1;
            if (rd < 1.0f) rd = 1.0f;
            out[0] = -(v / (float)c) * rd;

            atomicExch(&g_acc, 0ull);   // reset for next graph replay (off-path)
        }
    }
}

extern "C" void kernel_launch(void* const* d_in, const int* in_sizes, int n_in,
                              void* d_out, int out_size) {
    const float* inp     = (const float*)d_in[0];   // [B, L, V] f32
    const int*   tgt     = (const int*)  d_in[1];   // [B, S]    i32
    const float* reward  = (const float*)d_in[2];   // [1]       f32
    const float* reward1 = (const float*)d_in[3];   // [1]       f32
    float*       out     = (float*)d_out;           // [1]       f32

    scst_onepass_kernel<<<NBLK, 256>>>(inp, tgt, reward, reward1, out);
}